// round 5
// baseline (speedup 1.0000x reference)
#include <cuda_runtime.h>
#include <cuda_bf16.h>

#define NPTS   100000
#define GROUPS 12500
#define TPB    256
#define NCTA   152

#define WKV_LD 152
#define QW_LD  136
#define NF_LD  152
#define XA_LD  136
#define Y_LD   132

// smem byte offsets
#define OFF_WKV   0         // 256*152*2 = 77824
#define OFF_QW    77824     // 128*136*2 = 34816
#define OFF_LW    112640    // 34816
#define OFF_NF    147456    // 8*16*152*2 = 38912
#define OFF_XA    186368    // 16*136*2 = 4352
#define OFF_Q     190720    // 8*128*2 = 2048
#define OFF_XF    192768    // 8*128*4 = 4096
#define OFF_X1    196864    // 4096
#define OFF_AF    200960    // 4096
#define OFF_Y     205056    // 8*132*4 = 4224
#define OFF_BIAS  209280    // 1024*4 = 4096
#define SMEM_TOTAL 213376

#define SCALE 0.08838834764831845f   // 1/sqrt(128)

static __device__ __align__(16) __nv_bfloat16 g_wkv[256 * WKV_LD];
static __device__ __align__(16) __nv_bfloat16 g_qwT[128 * QW_LD];
static __device__ __align__(16) __nv_bfloat16 g_lwT[128 * QW_LD];

// ---------------- prep: transpose weights to bf16 [n][k] ----------------
__global__ void prep_kernel(const float* __restrict__ qw, const float* __restrict__ kw,
                            const float* __restrict__ vw, const float* __restrict__ lw) {
    int stride = gridDim.x * blockDim.x;
    for (int i = blockIdx.x * blockDim.x + threadIdx.x; i < 256 * WKV_LD; i += stride) {
        int n = i / WKV_LD, k = i - n * WKV_LD;
        float v = 0.f;
        if (k < 131) v = (n < 128) ? kw[k * 128 + n] : vw[k * 128 + (n - 128)];
        g_wkv[i] = __float2bfloat16_rn(v);
    }
    for (int i = blockIdx.x * blockDim.x + threadIdx.x; i < 128 * QW_LD; i += stride) {
        int n = i / QW_LD, k = i - n * QW_LD;
        g_qwT[i] = __float2bfloat16_rn(k < 128 ? qw[k * 128 + n] : 0.f);
        g_lwT[i] = __float2bfloat16_rn(k < 128 ? lw[k * 128 + n] : 0.f);
    }
}

// ---------------- device helpers ----------------
__device__ __forceinline__ unsigned s2u(const void* p) {
    return (unsigned)__cvta_generic_to_shared(p);
}
__device__ __forceinline__ void ldsm4(unsigned& r0, unsigned& r1, unsigned& r2, unsigned& r3,
                                      unsigned a) {
    asm volatile("ldmatrix.sync.aligned.m8n8.x4.shared.b16 {%0,%1,%2,%3},[%4];"
                 : "=r"(r0), "=r"(r1), "=r"(r2), "=r"(r3) : "r"(a));
}
__device__ __forceinline__ void mma16816(float* c, unsigned a0, unsigned a1, unsigned a2,
                                         unsigned a3, unsigned b0, unsigned b1) {
    asm volatile(
        "mma.sync.aligned.m16n8k16.row.col.f32.bf16.bf16.f32 "
        "{%0,%1,%2,%3},{%4,%5,%6,%7},{%8,%9},{%0,%1,%2,%3};"
        : "+f"(c[0]), "+f"(c[1]), "+f"(c[2]), "+f"(c[3])
        : "r"(a0), "r"(a1), "r"(a2), "r"(a3), "r"(b0), "r"(b1));
}
// A[16 x 152-pad] @ W^T(16 n-rows per np, 9 k-tiles) -> acc[16 ntiles][4]
__device__ __forceinline__ void proj16(float acc[16][4], unsigned aBase, unsigned bBase) {
#pragma unroll
    for (int kt = 0; kt < 9; kt++) {
        unsigned a0, a1, a2, a3;
        ldsm4(a0, a1, a2, a3, aBase + kt * 32);
#pragma unroll
        for (int np = 0; np < 8; np++) {
            unsigned b0, b1, b2, b3;
            ldsm4(b0, b1, b2, b3, bBase + np * (16 * WKV_LD * 2) + kt * 32);
            mma16816(acc[2 * np], a0, a1, a2, a3, b0, b2);
            mma16816(acc[2 * np + 1], a0, a1, a2, a3, b1, b3);
        }
    }
}
// [16x128] @ 16 cols of W^T (2 ntiles), 8 k-tiles
__device__ __forceinline__ void gemm2(float acc[2][4], unsigned aBase, unsigned bBase) {
#pragma unroll
    for (int kt = 0; kt < 8; kt++) {
        unsigned a0, a1, a2, a3, b0, b1, b2, b3;
        ldsm4(a0, a1, a2, a3, aBase + kt * 32);
        ldsm4(b0, b1, b2, b3, bBase + kt * 32);
        mma16816(acc[0], a0, a1, a2, a3, b0, b2);
        mma16816(acc[1], a0, a1, a2, a3, b1, b3);
    }
}
__device__ __forceinline__ float wsum(float v) {
    v += __shfl_xor_sync(~0u, v, 16);
    v += __shfl_xor_sync(~0u, v, 8);
    v += __shfl_xor_sync(~0u, v, 4);
    v += __shfl_xor_sync(~0u, v, 2);
    v += __shfl_xor_sync(~0u, v, 1);
    return v;
}

// ---------------- fused kernel ----------------
__global__ void __launch_bounds__(TPB, 1)
fused_kernel(const float* __restrict__ x, const float* __restrict__ feat,
             const float* __restrict__ xyz,
             const float* __restrict__ qb, const float* __restrict__ kb,
             const float* __restrict__ vb, const float* __restrict__ lb,
             const float* __restrict__ g1, const float* __restrict__ b1,
             const float* __restrict__ g2, const float* __restrict__ b2,
             float* __restrict__ out) {
    extern __shared__ char sm[];
    __nv_bfloat16* s_wkv = (__nv_bfloat16*)(sm + OFF_WKV);
    __nv_bfloat16* s_qw  = (__nv_bfloat16*)(sm + OFF_QW);
    __nv_bfloat16* s_lw  = (__nv_bfloat16*)(sm + OFF_LW);
    __nv_bfloat16* s_nf  = (__nv_bfloat16*)(sm + OFF_NF);
    __nv_bfloat16* s_xa  = (__nv_bfloat16*)(sm + OFF_XA);
    __nv_bfloat16* s_q   = (__nv_bfloat16*)(sm + OFF_Q);
    float* s_xf   = (float*)(sm + OFF_XF);
    float* s_x1   = (float*)(sm + OFF_X1);
    float* s_af   = (float*)(sm + OFF_AF);
    float* s_y    = (float*)(sm + OFF_Y);
    float* s_bias = (float*)(sm + OFF_BIAS);

    const int tid = threadIdx.x;
    const int w = tid >> 5;
    const int lane = tid & 31;

    // weights: device-global -> smem (uint4 copies)
    {
        uint4* d0 = (uint4*)s_wkv; const uint4* src0 = (const uint4*)g_wkv;
        for (int i = tid; i < 256 * WKV_LD / 8; i += TPB) d0[i] = src0[i];
        uint4* d1 = (uint4*)s_qw; const uint4* src1 = (const uint4*)g_qwT;
        for (int i = tid; i < 128 * QW_LD / 8; i += TPB) d1[i] = src1[i];
        uint4* d2 = (uint4*)s_lw; const uint4* src2 = (const uint4*)g_lwT;
        for (int i = tid; i < 128 * QW_LD / 8; i += TPB) d2[i] = src2[i];
    }
    {
        const float* srcs[8] = {qb, kb, vb, lb, g1, b1, g2, b2};
        for (int i = tid; i < 1024; i += TPB) s_bias[i] = srcs[i >> 7][i & 127];
    }
    // zero pads once (rows 8-15 of s_xa; cols >=131 of s_nf)
    for (int i = tid; i < 16 * XA_LD; i += TPB) s_xa[i] = __float2bfloat16(0.f);
    for (int i = tid; i < 8 * 16 * NF_LD; i += TPB) s_nf[i] = __float2bfloat16(0.f);
    __syncthreads();

    const float* s_kbias = s_bias + 128;
    const float* s_vbias = s_bias + 256;
    const float* s_lbias = s_bias + 384;
    const float* s_g1 = s_bias + 512;
    const float* s_b1 = s_bias + 640;
    const float* s_g2 = s_bias + 768;
    const float* s_b2 = s_bias + 896;

    const int tc = (lane & 3) * 2;          // col pair offset in C-frag
    const int h1 = lane >> 4;               // head context of row t/4
    const unsigned aQ  = s2u(s_xa) + (lane & 15) * (XA_LD * 2) + (lane >> 4) * 16;
    const unsigned bQ  = s2u(s_qw) + (w * 16 + (lane & 15)) * (QW_LD * 2) + (lane >> 4) * 16;
    const unsigned bL  = s2u(s_lw) + (w * 16 + (lane & 15)) * (QW_LD * 2) + (lane >> 4) * 16;
    const unsigned aNf = s2u(s_nf + w * 16 * NF_LD) + (lane & 15) * (NF_LD * 2) + (lane >> 4) * 16;
    const unsigned bK  = s2u(s_wkv) + (lane & 15) * (WKV_LD * 2) + (lane >> 4) * 16;
    const unsigned bV  = bK + 128 * (WKV_LD * 2);

    for (int g = blockIdx.x; g < GROUPS; g += gridDim.x) {
        const int n0 = g * 8;
        // ---- load x (warp-own row) ----
        {
            float4 v = ((const float4*)(x + (size_t)(n0 + w) * 128))[lane];
            ((float4*)(s_xf + w * 128))[lane] = v;
            *(__nv_bfloat162*)(s_xa + w * XA_LD + 4 * lane) = __floats2bfloat162_rn(v.x, v.y);
            *(__nv_bfloat162*)(s_xa + w * XA_LD + 4 * lane + 2) = __floats2bfloat162_rn(v.z, v.w);
        }
        // ---- load nf = [feat | xyz] (warp-own 16x131) ----
        {
            const float4* f4 = (const float4*)(feat + (size_t)(n0 + w) * 2048);
            __nv_bfloat16* nf = s_nf + w * 16 * NF_LD;
#pragma unroll
            for (int i = 0; i < 16; i++) {
                float4 v = f4[i * 32 + lane];
                *(__nv_bfloat162*)(nf + i * NF_LD + 4 * lane) = __floats2bfloat162_rn(v.x, v.y);
                *(__nv_bfloat162*)(nf + i * NF_LD + 4 * lane + 2) = __floats2bfloat162_rn(v.z, v.w);
            }
            if (lane < 16) {
                const float* xz = xyz + (size_t)(n0 + w) * 48 + lane * 3;
                nf[lane * NF_LD + 128] = __float2bfloat16_rn(xz[0]);
                nf[lane * NF_LD + 129] = __float2bfloat16_rn(xz[1]);
                nf[lane * NF_LD + 130] = __float2bfloat16_rn(xz[2]);
            }
        }
        __syncthreads();

        // ---- Q gemm: warp w -> cols [16w,16w+16) for the 8 points ----
        {
            float acc[2][4] = {};
            gemm2(acc, aQ, bQ);
            int r = lane >> 2;
#pragma unroll
            for (int nt = 0; nt < 2; nt++) {
                int c = w * 16 + nt * 8 + tc;
                *(__nv_bfloat162*)(s_q + r * 128 + c) =
                    __floats2bfloat162_rn(acc[nt][0] + s_bias[c], acc[nt][1] + s_bias[c + 1]);
            }
        }
        // ---- K projection (regs) ----
        float accK[16][4] = {};
        proj16(accK, aNf, bK);
#pragma unroll
        for (int nt = 0; nt < 16; nt++) {
            float kb0 = s_kbias[nt * 8 + tc], kb1 = s_kbias[nt * 8 + tc + 1];
            accK[nt][0] += kb0; accK[nt][1] += kb1;
            accK[nt][2] += kb0; accK[nt][3] += kb1;
        }
        __syncthreads();   // s_q ready

        // ---- attention scores from accK + s_q ----
        float qv1[8], qv2[8];
#pragma unroll
        for (int m = 0; m < 4; m++)
#pragma unroll
            for (int b = 0; b < 2; b++) {
                int d = 8 * m + tc + b;
                qv1[2 * m + b] = __bfloat162float(s_q[w * 128 + h1 * 32 + d]);
                qv2[2 * m + b] = __bfloat162float(s_q[w * 128 + (h1 + 2) * 32 + d]);
            }
        float sc1[4], sc2[4];
#pragma unroll
        for (int cb = 0; cb < 4; cb++) {
            float a = 0.f, b = 0.f;
#pragma unroll
            for (int m = 0; m < 4; m++) {
                int nt = 4 * cb + m;
                a += accK[nt][0] * qv1[2 * m] + accK[nt][1] * qv1[2 * m + 1];
                b += accK[nt][2] * qv2[2 * m] + accK[nt][3] * qv2[2 * m + 1];
            }
            a += __shfl_xor_sync(~0u, a, 1); a += __shfl_xor_sync(~0u, a, 2);
            b += __shfl_xor_sync(~0u, b, 1); b += __shfl_xor_sync(~0u, b, 2);
            sc1[cb] = a * SCALE; sc2[cb] = b * SCALE;
        }
        // softmax over kk (local cb + butterfly 4,8 across kkhi)
        float m1 = fmaxf(fmaxf(sc1[0], sc1[1]), fmaxf(sc1[2], sc1[3]));
        float m2 = fmaxf(fmaxf(sc2[0], sc2[1]), fmaxf(sc2[2], sc2[3]));
        m1 = fmaxf(m1, __shfl_xor_sync(~0u, m1, 4)); m1 = fmaxf(m1, __shfl_xor_sync(~0u, m1, 8));
        m2 = fmaxf(m2, __shfl_xor_sync(~0u, m2, 4)); m2 = fmaxf(m2, __shfl_xor_sync(~0u, m2, 8));
        float e1[4], e2[4], sum1 = 0.f, sum2 = 0.f;
#pragma unroll
        for (int cb = 0; cb < 4; cb++) {
            e1[cb] = __expf(sc1[cb] - m1); sum1 += e1[cb];
            e2[cb] = __expf(sc2[cb] - m2); sum2 += e2[cb];
        }
        sum1 += __shfl_xor_sync(~0u, sum1, 4); sum1 += __shfl_xor_sync(~0u, sum1, 8);
        sum2 += __shfl_xor_sync(~0u, sum2, 4); sum2 += __shfl_xor_sync(~0u, sum2, 8);
        float inv1 = 1.f / sum1, inv2 = 1.f / sum2;

        // ---- V projection + att_feat ----
        float accV[16][4] = {};
        proj16(accV, aNf, bV);
        float af1[8] = {}, af2[8] = {};
#pragma unroll
        for (int nt = 0; nt < 16; nt++) {
            float vb0 = s_vbias[nt * 8 + tc], vb1 = s_vbias[nt * 8 + tc + 1];
            float p1 = e1[nt >> 2] * inv1, p2 = e2[nt >> 2] * inv2;
            int m = nt & 3;
            af1[2 * m]     += p1 * (accV[nt][0] + vb0);
            af1[2 * m + 1] += p1 * (accV[nt][1] + vb1);
            af2[2 * m]     += p2 * (accV[nt][2] + vb0);
            af2[2 * m + 1] += p2 * (accV[nt][3] + vb1);
        }
#pragma unroll
        for (int i = 0; i < 8; i++) {
            af1[i] += __shfl_xor_sync(~0u, af1[i], 4);
            af1[i] += __shfl_xor_sync(~0u, af1[i], 8);
            af2[i] += __shfl_xor_sync(~0u, af2[i], 4);
            af2[i] += __shfl_xor_sync(~0u, af2[i], 8);
        }
        if (((lane >> 2) & 3) == 0) {
#pragma unroll
            for (int m = 0; m < 4; m++)
#pragma unroll
                for (int b = 0; b < 2; b++) {
                    int d = 8 * m + tc + b;
                    s_af[w * 128 + h1 * 32 + d] = af1[2 * m + b];
                    s_af[w * 128 + (h1 + 2) * 32 + d] = af2[2 * m + b];
                }
        }
        __syncwarp();

        // ---- x1 = LN1(x + att_feat) ----
        {
            float v[4];
#pragma unroll
            for (int i = 0; i < 4; i++)
                v[i] = s_xf[w * 128 + 4 * lane + i] + s_af[w * 128 + 4 * lane + i];
            float mean = wsum(v[0] + v[1] + v[2] + v[3]) * (1.f / 128.f);
            float vs = 0.f;
#pragma unroll
            for (int i = 0; i < 4; i++) { float d = v[i] - mean; vs += d * d; }
            float var = wsum(vs) * (1.f / 128.f);
            float rs = rsqrtf(var + 1e-5f);
#pragma unroll
            for (int i = 0; i < 4; i++) {
                int c = 4 * lane + i;
                v[i] = (v[i] - mean) * rs * s_g1[c] + s_b1[c];
                s_x1[w * 128 + c] = v[i];
            }
            *(__nv_bfloat162*)(s_xa + w * XA_LD + 4 * lane) = __floats2bfloat162_rn(v[0], v[1]);
            *(__nv_bfloat162*)(s_xa + w * XA_LD + 4 * lane + 2) = __floats2bfloat162_rn(v[2], v[3]);
        }
        __syncthreads();

        // ---- linear layer + residual ----
        {
            float acc[2][4] = {};
            gemm2(acc, aQ, bL);
            int r = lane >> 2;
#pragma unroll
            for (int nt = 0; nt < 2; nt++) {
                int c = w * 16 + nt * 8 + tc;
                s_y[r * Y_LD + c]     = s_x1[r * 128 + c] + acc[nt][0] + s_lbias[c];
                s_y[r * Y_LD + c + 1] = s_x1[r * 128 + c + 1] + acc[nt][1] + s_lbias[c + 1];
            }
        }
        __syncthreads();

        // ---- LN2 + store ----
        {
            float v[4];
#pragma unroll
            for (int i = 0; i < 4; i++) v[i] = s_y[w * Y_LD + 4 * lane + i];
            float mean = wsum(v[0] + v[1] + v[2] + v[3]) * (1.f / 128.f);
            float vs = 0.f;
#pragma unroll
            for (int i = 0; i < 4; i++) { float d = v[i] - mean; vs += d * d; }
            float rs = rsqrtf(wsum(vs) * (1.f / 128.f) + 1e-5f);
            float4 o;
            int c = 4 * lane;
            o.x = (v[0] - mean) * rs * s_g2[c] + s_b2[c];
            o.y = (v[1] - mean) * rs * s_g2[c + 1] + s_b2[c + 1];
            o.z = (v[2] - mean) * rs * s_g2[c + 2] + s_b2[c + 2];
            o.w = (v[3] - mean) * rs * s_g2[c + 3] + s_b2[c + 3];
            ((float4*)(out + (size_t)(n0 + w) * 128))[lane] = o;
        }
    }
}

// ---------------- launch ----------------
extern "C" void kernel_launch(void* const* d_in, const int* in_sizes, int n_in,
                              void* d_out, int out_size) {
    const float* x    = (const float*)d_in[0];
    const float* feat = (const float*)d_in[1];
    const float* xyz  = (const float*)d_in[2];
    const float* qw   = (const float*)d_in[3];
    const float* qb   = (const float*)d_in[4];
    const float* kw   = (const float*)d_in[5];
    const float* kb   = (const float*)d_in[6];
    const float* vw   = (const float*)d_in[7];
    const float* vb   = (const float*)d_in[8];
    const float* lw   = (const float*)d_in[9];
    const float* lb   = (const float*)d_in[10];
    const float* g1   = (const float*)d_in[11];
    const float* b1   = (const float*)d_in[12];
    const float* g2   = (const float*)d_in[13];
    const float* b2   = (const float*)d_in[14];
    float* out = (float*)d_out;

    cudaFuncSetAttribute(fused_kernel, cudaFuncAttributeMaxDynamicSharedMemorySize, SMEM_TOTAL);
    prep_kernel<<<128, 256>>>(qw, kw, vw, lw);
    fused_kernel<<<NCTA, TPB, SMEM_TOTAL>>>(x, feat, xyz, qb, kb, vb, lb, g1, b1, g2, b2, out);
}

// round 12
// speedup vs baseline: 1.4495x; 1.4495x over previous
#include <cuda_runtime.h>
#include <cuda_bf16.h>
#include <cstdint>

#define GROUPS 12500
#define NCTA   152
#define TPB    256
#define SCALE  0.08838834764831845f

// smem byte offsets
#define OFF_B    0        // 98304: combined [K|V] weights [256n x 192k] bf16, blocked SW128
#define OFF_NF0  98304    // 49152: A buf [128 x 192] bf16, blocked SW128
#define OFF_NF1  147456   // 49152
#define OFF_XA   196608   // 4352: x bf16 16x136 (rows 8-15 zero)
#define OFF_X1A  200960   // 4352
#define OFF_XF   205312   // 4096: x f32 8x128
#define OFF_Q    209408   // 4224: Q f32 8x132, later y
#define OFF_SC   213632   // 2048: scores [8p][4h][16kk]   (aliases X1F)
#define OFF_PROB 215680   // 2048: probs  [8p][4h][16kk]   (aliases X1F)
#define OFF_X1F  213632   // 4096: x1 f32 8x128 (aliases SC+PROB, disjoint lifetime)
#define OFF_AFP  217728   // 8192: af partials [2][8p][128c] f32
#define OFF_BIAS 225920   // 4096: qb,kb,vb,lb,g1,b1,g2,b2
#define OFF_SYS  230016   // tmem ptr @0, mbar0 @8, mbar1 @16
#define SMEM_TOTAL 230048

#define IDESC 0x08200490u   // f32 accum, bf16 x bf16, M=128, N=128

static __device__ __align__(16) unsigned char g_wkvB[98304];
static __device__ __align__(16) __nv_bfloat16 g_qwT[128 * 136];
static __device__ __align__(16) __nv_bfloat16 g_lwT[128 * 136];

__global__ void prep_kernel(const float* __restrict__ qw, const float* __restrict__ kw,
                            const float* __restrict__ vw, const float* __restrict__ lw) {
    int stride = gridDim.x * blockDim.x;
    for (int i = blockIdx.x * blockDim.x + threadIdx.x; i < 256 * 192; i += stride) {
        int n = i / 192, k = i - n * 192;
        float v = 0.f;
        if (k < 131) v = (n < 128) ? kw[k * 128 + n] : vw[k * 128 + (n - 128)];
        int off = ((n >> 3) + (k >> 6) * 32) * 1024 + (n & 7) * 128 + (k & 63) * 2;
        int sw = off ^ ((off >> 3) & 0x70);
        *(__nv_bfloat16*)(g_wkvB + sw) = __float2bfloat16_rn(v);
    }
    for (int i = blockIdx.x * blockDim.x + threadIdx.x; i < 128 * 136; i += stride) {
        int n = i / 136, k = i - n * 136;
        g_qwT[i] = __float2bfloat16_rn(k < 128 ? qw[k * 128 + n] : 0.f);
        g_lwT[i] = __float2bfloat16_rn(k < 128 ? lw[k * 128 + n] : 0.f);
    }
}

__device__ __forceinline__ unsigned s2u(const void* p) {
    return (unsigned)__cvta_generic_to_shared(p);
}
__device__ __forceinline__ unsigned elect1() {
    unsigned p;
    asm volatile("{\n\t.reg .pred p;\n\telect.sync _|p, 0xFFFFFFFF;\n\tselp.b32 %0,1,0,p;\n\t}"
                 : "=r"(p));
    return p;
}
__device__ __forceinline__ void ldsm4(unsigned& r0, unsigned& r1, unsigned& r2, unsigned& r3,
                                      unsigned a) {
    asm volatile("ldmatrix.sync.aligned.m8n8.x4.shared.b16 {%0,%1,%2,%3},[%4];"
                 : "=r"(r0), "=r"(r1), "=r"(r2), "=r"(r3) : "r"(a));
}
__device__ __forceinline__ void mma16816(float* c, unsigned a0, unsigned a1, unsigned a2,
                                         unsigned a3, unsigned b0, unsigned b1) {
    asm volatile(
        "mma.sync.aligned.m16n8k16.row.col.f32.bf16.bf16.f32 "
        "{%0,%1,%2,%3},{%4,%5,%6,%7},{%8,%9},{%0,%1,%2,%3};"
        : "+f"(c[0]), "+f"(c[1]), "+f"(c[2]), "+f"(c[3])
        : "r"(a0), "r"(a1), "r"(a2), "r"(a3), "r"(b0), "r"(b1));
}
__device__ __forceinline__ float wsum(float v) {
    v += __shfl_xor_sync(~0u, v, 16); v += __shfl_xor_sync(~0u, v, 8);
    v += __shfl_xor_sync(~0u, v, 4);  v += __shfl_xor_sync(~0u, v, 2);
    v += __shfl_xor_sync(~0u, v, 1);  return v;
}

#if defined(__CUDA_ARCH_FEAT_SM103_ALL) || defined(__CUDA_ARCH_FEAT_SM103A_ALL)
#define HAS_TCGEN05 1
#else
#define HAS_TCGEN05 0
#endif

#if HAS_TCGEN05
__device__ __forceinline__ void tc_mma(uint32_t d, uint64_t ad, uint64_t bd, uint32_t en) {
    asm volatile(
        "{\n\t.reg .pred p;\n\tsetp.ne.u32 p, %4, 0;\n\t"
        "tcgen05.mma.cta_group::1.kind::f16 [%0], %1, %2, %3, {%5,%5,%5,%5}, p;\n\t}"
        :: "r"(d), "l"(ad), "l"(bd), "r"(IDESC), "r"(en), "r"(0u) : "memory");
}
#define MBAR_INIT(a, c) \
    asm volatile("mbarrier.init.shared.b64 [%0], %1;" :: "r"(a), "r"(c) : "memory")
#define MBAR_WAIT(a, ph) \
    asm volatile("{\n\t.reg .pred P1;\n\tWL%=:\n\t" \
        "mbarrier.try_wait.parity.acquire.cta.shared::cta.b64 P1,[%0],%1,0x989680;\n\t" \
        "@P1 bra.uni WD%=;\n\tbra.uni WL%=;\n\tWD%=:\n\t}" :: "r"(a), "r"(ph) : "memory")
#define TC_COMMIT(mb) \
    asm volatile("tcgen05.commit.cta_group::1.mbarrier::arrive::one.shared::cluster.b64 [%0];" \
                 :: "r"(mb) : "memory")
#define TC_ALLOC(a, n) \
    asm volatile("tcgen05.alloc.cta_group::1.sync.aligned.shared::cta.b32 [%0], %1;" \
                 :: "r"(a), "r"(n) : "memory")
#define TC_DEALLOC(t, n) \
    asm volatile("tcgen05.dealloc.cta_group::1.sync.aligned.b32 %0, %1;" :: "r"(t), "r"(n))
#define TC_RELINQ() asm volatile("tcgen05.relinquish_alloc_permit.cta_group::1.sync.aligned;")
#define TC_FENCE_AFTER() asm volatile("tcgen05.fence::after_thread_sync;" ::: "memory")
#define TC_WAIT_LD() asm volatile("tcgen05.wait::ld.sync.aligned;" ::: "memory")
#define FENCE_PROXY() asm volatile("fence.proxy.async.shared::cta;" ::: "memory")
#define TC_LD32(r, a) \
    asm volatile("tcgen05.ld.sync.aligned.32x32b.x32.b32 " \
        "{%0,%1,%2,%3,%4,%5,%6,%7,%8,%9,%10,%11,%12,%13,%14,%15," \
        "%16,%17,%18,%19,%20,%21,%22,%23,%24,%25,%26,%27,%28,%29,%30,%31},[%32];" \
        : "=r"((r)[0]),"=r"((r)[1]),"=r"((r)[2]),"=r"((r)[3]),"=r"((r)[4]),"=r"((r)[5]), \
          "=r"((r)[6]),"=r"((r)[7]),"=r"((r)[8]),"=r"((r)[9]),"=r"((r)[10]),"=r"((r)[11]), \
          "=r"((r)[12]),"=r"((r)[13]),"=r"((r)[14]),"=r"((r)[15]),"=r"((r)[16]),"=r"((r)[17]), \
          "=r"((r)[18]),"=r"((r)[19]),"=r"((r)[20]),"=r"((r)[21]),"=r"((r)[22]),"=r"((r)[23]), \
          "=r"((r)[24]),"=r"((r)[25]),"=r"((r)[26]),"=r"((r)[27]),"=r"((r)[28]),"=r"((r)[29]), \
          "=r"((r)[30]),"=r"((r)[31]) : "r"(a))
#endif

static constexpr uint64_t DESC_BASE =
    (uint64_t(2) << 61) | (uint64_t(1) << 46) | (uint64_t(64) << 32) | (uint64_t(1) << 16);

__global__ void __launch_bounds__(TPB, 1)
fused_kernel(const float* __restrict__ x, const float* __restrict__ feat,
             const float* __restrict__ xyz,
             const float* __restrict__ qb, const float* __restrict__ kb,
             const float* __restrict__ vb, const float* __restrict__ lb,
             const float* __restrict__ g1, const float* __restrict__ b1,
             const float* __restrict__ g2, const float* __restrict__ b2,
             float* __restrict__ out) {
#if HAS_TCGEN05
    extern __shared__ char sm[];
    __nv_bfloat16* s_xa  = (__nv_bfloat16*)(sm + OFF_XA);
    __nv_bfloat16* s_x1a = (__nv_bfloat16*)(sm + OFF_X1A);
    float* s_xf  = (float*)(sm + OFF_XF);
    float* s_q   = (float*)(sm + OFF_Q);
    float* s_sc  = (float*)(sm + OFF_SC);
    float* s_pr  = (float*)(sm + OFF_PROB);
    float* s_x1f = (float*)(sm + OFF_X1F);
    float* s_afp = (float*)(sm + OFF_AFP);
    float* s_bias = (float*)(sm + OFF_BIAS);
    const unsigned sysb = s2u(sm + OFF_SYS);

    const int tid = threadIdx.x, w = tid >> 5, lane = tid & 31;

    if (w == 0) { TC_ALLOC(sysb, 512); TC_RELINQ(); }
    if (tid == 0) { MBAR_INIT(sysb + 8, 1); MBAR_INIT(sysb + 16, 1); }

    // stage qw->NF0, lw->NF1; load persistent Q/lin B-fragments
    {
        uint4* dq = (uint4*)(sm + OFF_NF0); const uint4* sq = (const uint4*)g_qwT;
        uint4* dl = (uint4*)(sm + OFF_NF1); const uint4* sl = (const uint4*)g_lwT;
        for (int i = tid; i < 128 * 136 / 8; i += TPB) { dq[i] = sq[i]; dl[i] = sl[i]; }
    }
    __syncthreads();
    unsigned fq[8][4], fl[8][4];
    {
        unsigned bq = s2u(sm + OFF_NF0) + (w * 16 + (lane & 15)) * 272 + (lane >> 4) * 16;
        unsigned bl = s2u(sm + OFF_NF1) + (w * 16 + (lane & 15)) * 272 + (lane >> 4) * 16;
#pragma unroll
        for (int kt = 0; kt < 8; kt++) {
            ldsm4(fq[kt][0], fq[kt][1], fq[kt][2], fq[kt][3], bq + kt * 32);
            ldsm4(fl[kt][0], fl[kt][1], fl[kt][2], fl[kt][3], bl + kt * 32);
        }
    }
    __syncthreads();
    // B weights, zero NF bufs, biases, zero pad rows of XA/X1A
    {
        uint4* db = (uint4*)(sm + OFF_B); const uint4* sb = (const uint4*)g_wkvB;
        for (int i = tid; i < 98304 / 16; i += TPB) db[i] = sb[i];
        uint4 z = {0, 0, 0, 0};
        uint4* n0 = (uint4*)(sm + OFF_NF0); uint4* n1 = (uint4*)(sm + OFF_NF1);
        for (int i = tid; i < 49152 / 16; i += TPB) { n0[i] = z; n1[i] = z; }
        const float* srcs[8] = {qb, kb, vb, lb, g1, b1, g2, b2};
        for (int i = tid; i < 1024; i += TPB) s_bias[i] = srcs[i >> 7][i & 127];
        for (int i = tid; i < 16 * 136; i += TPB) {
            s_xa[i] = __float2bfloat16(0.f); s_x1a[i] = __float2bfloat16(0.f);
        }
    }
    __syncthreads();

    unsigned tmem;
    asm volatile("ld.shared.b32 %0,[%1];" : "=r"(tmem) : "r"(sysb));

    const uint64_t bdesc = DESC_BASE | (((uint64_t)(s2u(sm + OFF_B)) >> 4) & 0x3FFF);
    const unsigned aQ = s2u(s_xa) + (lane & 15) * 272 + (lane >> 4) * 16;
    const unsigned aL = s2u(s_x1a) + (lane & 15) * 272 + (lane >> 4) * 16;
    const int tc = (lane & 3) * 2;
    const float* kbv = s_bias + 128;
    const float* vbv = s_bias + 256;

    auto load_feat = [&](int g, int buf) {
        const char* ab = sm + (buf ? OFF_NF1 : OFF_NF0);
        size_t base = (size_t)g * 2048 * 8;
#pragma unroll
        for (int j = 0; j < 8; j++) {
            int cid = tid + j * 256;
            int row = cid >> 4, c0 = (cid & 15) * 8;
            const float4* src = (const float4*)(feat + base + (size_t)row * 128 + c0);
            float4 u = src[0], v = src[1];
            int off = ((row >> 3) + (c0 >> 6) * 16) * 1024 + (row & 7) * 128 + (c0 & 63) * 2;
            int swo = off ^ ((off >> 3) & 0x70);
            __nv_bfloat162 p0 = __floats2bfloat162_rn(u.x, u.y);
            __nv_bfloat162 p1 = __floats2bfloat162_rn(u.z, u.w);
            __nv_bfloat162 p2 = __floats2bfloat162_rn(v.x, v.y);
            __nv_bfloat162 p3 = __floats2bfloat162_rn(v.z, v.w);
            uint4 pk;
            pk.x = *(unsigned*)&p0; pk.y = *(unsigned*)&p1;
            pk.z = *(unsigned*)&p2; pk.w = *(unsigned*)&p3;
            *(uint4*)(ab + swo) = pk;
        }
        if (tid < 128) {
            int row = tid;
            const float* xz = xyz + (size_t)(g * 8 + (row >> 4)) * 48 + (row & 15) * 3;
            int off = ((row >> 3) + 32) * 1024 + (row & 7) * 128;
            int swo = off ^ ((off >> 3) & 0x70);
            __nv_bfloat16* dst = (__nv_bfloat16*)(ab + swo);
            dst[0] = __float2bfloat16_rn(xz[0]);
            dst[1] = __float2bfloat16_rn(xz[1]);
            dst[2] = __float2bfloat16_rn(xz[2]);
        }
        FENCE_PROXY();
    };
    auto load_x = [&](int g) {
        float4 v = ((const float4*)(x + (size_t)(g * 8 + w) * 128))[lane];
        ((float4*)(s_xf + w * 128))[lane] = v;
        *(__nv_bfloat162*)(s_xa + w * 136 + 4 * lane) = __floats2bfloat162_rn(v.x, v.y);
        *(__nv_bfloat162*)(s_xa + w * 136 + 4 * lane + 2) = __floats2bfloat162_rn(v.z, v.w);
    };

    int g0 = blockIdx.x;
    if (g0 < GROUPS) { load_feat(g0, 0); load_x(g0); }
    __syncthreads();

    const int sub = w & 3, half = w >> 2;
    const int p0 = 2 * sub + (lane >> 4);
    const int rr = lane & 15, hh = rr >> 2, qq = rr & 3;

    int it = 0;
    for (int g = g0; g < GROUPS; g += NCTA, it++) {
        const int b = it & 1;
        const unsigned dK = tmem + b * 256, dV = dK + 128;
        if (w == 0) {
            if (elect1()) {
                uint64_t ad = DESC_BASE |
                    (((uint64_t)(s2u(sm + (b ? OFF_NF1 : OFF_NF0))) >> 4) & 0x3FFF);
#pragma unroll
                for (int s = 0; s < 9; s++) {
                    uint64_t ao = (uint64_t)((s >> 2) * 1024 + (s & 3) * 2);
                    uint64_t bo = (uint64_t)((s >> 2) * 2048 + (s & 3) * 2);
                    tc_mma(dK, ad + ao, bdesc + bo, s > 0);
                    tc_mma(dV, ad + ao, bdesc + 1024 + bo, s > 0);
                }
                TC_COMMIT(sysb + 8 + b * 8);
            }
        }
        if (g + NCTA < GROUPS) load_feat(g + NCTA, b ^ 1);
        // Q gemm -> s_q f32 [8 x 132]
        {
            float acc[2][4] = {};
#pragma unroll
            for (int kt = 0; kt < 8; kt++) {
                unsigned a0, a1, a2, a3;
                ldsm4(a0, a1, a2, a3, aQ + kt * 32);
                mma16816(acc[0], a0, a1, a2, a3, fq[kt][0], fq[kt][2]);
                mma16816(acc[1], a0, a1, a2, a3, fq[kt][1], fq[kt][3]);
            }
            int r = lane >> 2;
#pragma unroll
            for (int nt = 0; nt < 2; nt++) {
                int c = w * 16 + nt * 8 + tc;
                s_q[r * 132 + c]     = acc[nt][0] + s_bias[c];
                s_q[r * 132 + c + 1] = acc[nt][1] + s_bias[c + 1];
            }
        }
        __syncthreads();
        MBAR_WAIT(sysb + 8 + b * 8, (it >> 1) & 1);
        TC_FENCE_AFTER();

        // scores: Kt[p,h,kk,d] = KM[p, 4h+(kk>>2), 32(kk&3)+d]
#pragma unroll
        for (int t = 0; t < 2; t++) {
            int cb = half * 2 + t;
            unsigned r[32];
            TC_LD32(r, dK + 32 * cb);
            TC_WAIT_LD();
            float sc = 0.f;
            const float* qrow = s_q + p0 * 132 + 32 * hh;
#pragma unroll
            for (int j = 0; j < 32; j++)
                sc += (__uint_as_float(r[j]) + kbv[32 * cb + j]) * qrow[j];
            s_sc[p0 * 64 + hh * 16 + 4 * qq + cb] = sc * SCALE;
        }
        __syncthreads();
        // coop softmax: warp w -> point w
        {
            float v0 = s_sc[w * 64 + lane];
            float v1 = s_sc[w * 64 + 32 + lane];
            float m0 = v0, m1 = v1;
#pragma unroll
            for (int msk = 8; msk >= 1; msk >>= 1) {
                m0 = fmaxf(m0, __shfl_xor_sync(~0u, m0, msk));
                m1 = fmaxf(m1, __shfl_xor_sync(~0u, m1, msk));
            }
            float e0 = __expf(v0 - m0), e1 = __expf(v1 - m1);
            float t0 = e0, t1 = e1;
#pragma unroll
            for (int msk = 8; msk >= 1; msk >>= 1) {
                t0 += __shfl_xor_sync(~0u, t0, msk);
                t1 += __shfl_xor_sync(~0u, t1, msk);
            }
            s_pr[w * 64 + lane] = e0 / t0;
            s_pr[w * 64 + 32 + lane] = e1 / t1;
        }
        __syncthreads();
        // att_feat partials
        {
            float afl[32];
#pragma unroll
            for (int j = 0; j < 32; j++) afl[j] = 0.f;
#pragma unroll
            for (int t = 0; t < 2; t++) {
                int cb = half * 2 + t;
                unsigned r[32];
                TC_LD32(r, dV + 32 * cb);
                TC_WAIT_LD();
                float pr = s_pr[p0 * 64 + hh * 16 + 4 * qq + cb];
#pragma unroll
                for (int j = 0; j < 32; j++) afl[j] += pr * __uint_as_float(r[j]);
            }
#pragma unroll
            for (int j = 0; j < 32; j++) {
                afl[j] += __shfl_xor_sync(~0u, afl[j], 1);
                afl[j] += __shfl_xor_sync(~0u, afl[j], 2);
            }
            if (qq == 0) {
                float* dst = s_afp + half * 1024 + p0 * 128 + 32 * hh;
#pragma unroll
                for (int j = 0; j < 32; j++) dst[j] = afl[j];
            }
        }
        __syncthreads();
        // LN1 (warp = point w); writes s_x1f (overwrites SC/PROB region)
        {
            float v[4];
#pragma unroll
            for (int i = 0; i < 4; i++) {
                int c = 4 * lane + i;
                v[i] = s_xf[w * 128 + c] + s_afp[w * 128 + c] + s_afp[1024 + w * 128 + c] +
                       vbv[c];
            }
            float mean = wsum(v[0] + v[1] + v[2] + v[3]) * (1.f / 128.f);
            float vs = 0.f;
#pragma unroll
            for (int i = 0; i < 4; i++) { float d = v[i] - mean; vs += d * d; }
            float rs = rsqrtf(wsum(vs) * (1.f / 128.f) + 1e-5f);
#pragma unroll
            for (int i = 0; i < 4; i++) {
                int c = 4 * lane + i;
                v[i] = (v[i] - mean) * rs * s_bias[512 + c] + s_bias[640 + c];
                s_x1f[w * 128 + c] = v[i];
            }
            *(__nv_bfloat162*)(s_x1a + w * 136 + 4 * lane) = __floats2bfloat162_rn(v[0], v[1]);
            *(__nv_bfloat162*)(s_x1a + w * 136 + 4 * lane + 2) = __floats2bfloat162_rn(v[2], v[3]);
        }
        __syncthreads();
        if (g + NCTA < GROUPS) load_x(g + NCTA);
        // lin gemm + residual -> s_q (as y)
        {
            float acc[2][4] = {};
#pragma unroll
            for (int kt = 0; kt < 8; kt++) {
                unsigned a0, a1, a2, a3;
                ldsm4(a0, a1, a2, a3, aL + kt * 32);
                mma16816(acc[0], a0, a1, a2, a3, fl[kt][0], fl[kt][2]);
                mma16816(acc[1], a0, a1, a2, a3, fl[kt][1], fl[kt][3]);
            }
            int r = lane >> 2;
#pragma unroll
            for (int nt = 0; nt < 2; nt++) {
                int c = w * 16 + nt * 8 + tc;
                s_q[r * 132 + c]     = s_x1f[r * 128 + c] + acc[nt][0] + s_bias[384 + c];
                s_q[r * 132 + c + 1] = s_x1f[r * 128 + c + 1] + acc[nt][1] + s_bias[384 + c + 1];
            }
        }
        __syncthreads();
        // LN2 + store
        {
            float v[4];
#pragma unroll
            for (int i = 0; i < 4; i++) v[i] = s_q[w * 132 + 4 * lane + i];
            float mean = wsum(v[0] + v[1] + v[2] + v[3]) * (1.f / 128.f);
            float vs = 0.f;
#pragma unroll
            for (int i = 0; i < 4; i++) { float d = v[i] - mean; vs += d * d; }
            float rs = rsqrtf(wsum(vs) * (1.f / 128.f) + 1e-5f);
            float4 o; int c = 4 * lane;
            o.x = (v[0] - mean) * rs * s_bias[768 + c] + s_bias[896 + c];
            o.y = (v[1] - mean) * rs * s_bias[768 + c + 1] + s_bias[896 + c + 1];
            o.z = (v[2] - mean) * rs * s_bias[768 + c + 2] + s_bias[896 + c + 2];
            o.w = (v[3] - mean) * rs * s_bias[768 + c + 3] + s_bias[896 + c + 3];
            ((float4*)(out + (size_t)(g * 8 + w) * 128))[lane] = o;
        }
        __syncthreads();
    }
    __syncthreads();
    if (w == 0) TC_DEALLOC(tmem, 512);
#endif
}

extern "C" void kernel_launch(void* const* d_in, const int* in_sizes, int n_in,
                              void* d_out, int out_size) {
    const float* x    = (const float*)d_in[0];
    const float* feat = (const float*)d_in[1];
    const float* xyz  = (const float*)d_in[2];
    const float* qw   = (const float*)d_in[3];
    const float* qb   = (const float*)d_in[4];
    const float* kw   = (const float*)d_in[5];
    const float* kb   = (const float*)d_in[6];
    const float* vw   = (const float*)d_in[7];
    const float* vb   = (const float*)d_in[8];
    const float* lw   = (const float*)d_in[9];
    const float* lb   = (const float*)d_in[10];
    const float* g1   = (const float*)d_in[11];
    const float* b1   = (const float*)d_in[12];
    const float* g2   = (const float*)d_in[13];
    const float* b2   = (const float*)d_in[14];
    float* out = (float*)d_out;
    cudaFuncSetAttribute(fused_kernel, cudaFuncAttributeMaxDynamicSharedMemorySize, SMEM_TOTAL);
    prep_kernel<<<128, 256>>>(qw, kw, vw, lw);
    fused_kernel<<<NCTA, TPB, SMEM_TOTAL>>>(x, feat, xyz, qb, kb, vb, lb, g1, b1, g2, b2, out);
}